// round 9
// baseline (speedup 1.0000x reference)
#include <cuda_runtime.h>

// Problem constants
#define T_STEPS 100
#define BATCH   256
#define N_IN    1024
#define N_HID   4096
#define N_OUT   512
#define KHALF   (N_IN / 2)     // gemm1 split-K=2 boundary

#define BETA   0.95f
#define THRESH 1.0f

// ---------------------------------------------------------------------------
// RULE (learned in R4/R6): __device__ globals are referenced ONLY inside
// device code. Host passes integer indices, never shadow addresses.
// ---------------------------------------------------------------------------
__device__ float g_cur1[(size_t)T_STEPS * BATCH * N_HID];   // 419 MB (HBM now)
__device__ float g_mem1[BATCH * N_HID];
__device__ float g_spk1[BATCH * N_HID];
__device__ float g_mem2[BATCH * N_OUT];
__device__ float g_p[BATCH * N_OUT];

__global__ void init_kernel() {
    int i = blockIdx.x * blockDim.x + threadIdx.x;
    if (i < BATCH * N_HID) g_mem1[i] = 0.0f;
    if (i < BATCH * N_OUT) g_mem2[i] = 0.0f;
}

// ---------------------------------------------------------------------------
// GEMM1 with SPLIT-K=2 (this round's experimental variable):
//   p0 = chain over k in [0,512), p1 = chain over k in [512,1024)
//   cur1 = (p0 + p1) + b1     (cublasLt split-K reduce order, bias last)
// Tile 128x64x16, 256 threads, 8x4 per thread (two acc sets live).
// Output written directly to g_cur1 (device symbol, inside kernel).
// ---------------------------------------------------------------------------
__global__ __launch_bounds__(256) void gemm1_kernel(
    const float* __restrict__ A,     // [25600, N_IN]
    const float* __restrict__ W,     // [N_HID, N_IN]
    const float* __restrict__ bias)  // [N_HID]
{
    const int BK = 16;
    __shared__ float As[BK][128];
    __shared__ float Bs[BK][64];

    const int tid = threadIdx.x;
    const int m0 = blockIdx.y * 128;
    const int n0 = blockIdx.x * 64;
    const int tm = (tid >> 4) << 3;   // 0..120
    const int tn = (tid & 15) << 2;   // 0..60

    const int rB  = tid >> 2;         // 0..63  (B-tile row)
    const int kvB = (tid & 3) << 2;   // 0,4,8,12

    float accA[8][4], accB[8][4];
    #pragma unroll
    for (int i = 0; i < 8; i++)
        #pragma unroll
        for (int j = 0; j < 4; j++) { accA[i][j] = 0.0f; accB[i][j] = 0.0f; }

    // ---- first half: k in [0, 512) -> accA ----
    for (int k0 = 0; k0 < KHALF; k0 += BK) {
        #pragma unroll
        for (int i = 0; i < 2; i++) {
            int l  = tid + i * 256;
            int r  = l >> 2;
            int kv = (l & 3) << 2;
            float4 va = *(const float4*)(A + (size_t)(m0 + r) * N_IN + k0 + kv);
            As[kv + 0][r] = va.x; As[kv + 1][r] = va.y;
            As[kv + 2][r] = va.z; As[kv + 3][r] = va.w;
        }
        float4 vb = *(const float4*)(W + (size_t)(n0 + rB) * N_IN + k0 + kvB);
        Bs[kvB + 0][rB] = vb.x; Bs[kvB + 1][rB] = vb.y;
        Bs[kvB + 2][rB] = vb.z; Bs[kvB + 3][rB] = vb.w;
        __syncthreads();

        #pragma unroll
        for (int kk = 0; kk < BK; kk++) {
            float a[8], b[4];
            *(float4*)&a[0] = *(const float4*)&As[kk][tm];
            *(float4*)&a[4] = *(const float4*)&As[kk][tm + 4];
            *(float4*)&b[0] = *(const float4*)&Bs[kk][tn];
            #pragma unroll
            for (int i = 0; i < 8; i++)
                #pragma unroll
                for (int j = 0; j < 4; j++)
                    accA[i][j] = fmaf(a[i], b[j], accA[i][j]);
        }
        __syncthreads();
    }

    // ---- second half: k in [512, 1024) -> accB ----
    for (int k0 = KHALF; k0 < N_IN; k0 += BK) {
        #pragma unroll
        for (int i = 0; i < 2; i++) {
            int l  = tid + i * 256;
            int r  = l >> 2;
            int kv = (l & 3) << 2;
            float4 va = *(const float4*)(A + (size_t)(m0 + r) * N_IN + k0 + kv);
            As[kv + 0][r] = va.x; As[kv + 1][r] = va.y;
            As[kv + 2][r] = va.z; As[kv + 3][r] = va.w;
        }
        float4 vb = *(const float4*)(W + (size_t)(n0 + rB) * N_IN + k0 + kvB);
        Bs[kvB + 0][rB] = vb.x; Bs[kvB + 1][rB] = vb.y;
        Bs[kvB + 2][rB] = vb.z; Bs[kvB + 3][rB] = vb.w;
        __syncthreads();

        #pragma unroll
        for (int kk = 0; kk < BK; kk++) {
            float a[8], b[4];
            *(float4*)&a[0] = *(const float4*)&As[kk][tm];
            *(float4*)&a[4] = *(const float4*)&As[kk][tm + 4];
            *(float4*)&b[0] = *(const float4*)&Bs[kk][tn];
            #pragma unroll
            for (int i = 0; i < 8; i++)
                #pragma unroll
                for (int j = 0; j < 4; j++)
                    accB[i][j] = fmaf(a[i], b[j], accB[i][j]);
        }
        __syncthreads();
    }

    // epilogue: (p0 + p1) + bias
    float bv[4];
    *(float4*)&bv[0] = *(const float4*)&bias[n0 + tn];

    #pragma unroll
    for (int i = 0; i < 8; i++) {
        float o[4];
        #pragma unroll
        for (int j = 0; j < 4; j++)
            o[j] = __fadd_rn(__fadd_rn(accA[i][j], accB[i][j]), bv[j]);
        *(float4*)(g_cur1 + (size_t)(m0 + tm + i) * N_HID + n0 + tn) =
            make_float4(o[0], o[1], o[2], o[3]);
    }
}

// ---------------------------------------------------------------------------
// LIF update, de-contracted (matches XLA elementwise; proven flip-neutral
// vs contracted, keep the XLA-faithful form).
// ---------------------------------------------------------------------------
__device__ __forceinline__ void lif_update(float m, float c, float& nm, float& sp) {
    float t0 = __fmul_rn(BETA, m);
    float t1 = __fadd_rn(t0, c);
    float rst = (m > THRESH) ? THRESH : 0.0f;
    nm = __fsub_rn(t1, rst);
    sp = (nm > THRESH) ? 1.0f : 0.0f;
}

__global__ __launch_bounds__(256) void step1_kernel(int t) {
    const float* cur1_t = g_cur1 + (size_t)t * BATCH * N_HID;   // device-side
    int i = blockIdx.x * blockDim.x + threadIdx.x;
    float4 c = ((const float4*)cur1_t)[i];
    float4 m = ((const float4*)g_mem1)[i];
    float4 nm, sp;
    lif_update(m.x, c.x, nm.x, sp.x);
    lif_update(m.y, c.y, nm.y, sp.y);
    lif_update(m.z, c.z, nm.z, sp.z);
    lif_update(m.w, c.w, nm.w, sp.w);
    ((float4*)g_mem1)[i] = nm;
    ((float4*)g_spk1)[i] = sp;
}

// ---------------------------------------------------------------------------
// GEMM2 (unchanged from R8): single sequential ascending-k chain over 4096.
// Tile 64x64x16, 256 threads, 4x4 per thread. grid (8,4) = 32 blocks.
// ---------------------------------------------------------------------------
__global__ __launch_bounds__(256) void gemm2_kernel(const float* __restrict__ W2)
{
    const int BK = 16;
    __shared__ float As[BK][64];
    __shared__ float Bs[BK][64];

    const int tid = threadIdx.x;
    const int m0 = blockIdx.y * 64;
    const int n0 = blockIdx.x * 64;
    const int tm = (tid >> 4) << 2;
    const int tn = (tid & 15) << 2;

    float acc[4][4];
    #pragma unroll
    for (int i = 0; i < 4; i++)
        #pragma unroll
        for (int j = 0; j < 4; j++) acc[i][j] = 0.0f;

    const int r  = tid >> 2;
    const int kv = (tid & 3) << 2;

    for (int k0 = 0; k0 < N_HID; k0 += BK) {
        float4 va = *(const float4*)(g_spk1 + (size_t)(m0 + r) * N_HID + k0 + kv);
        As[kv + 0][r] = va.x; As[kv + 1][r] = va.y;
        As[kv + 2][r] = va.z; As[kv + 3][r] = va.w;
        float4 vb = *(const float4*)(W2 + (size_t)(n0 + r) * N_HID + k0 + kv);
        Bs[kv + 0][r] = vb.x; Bs[kv + 1][r] = vb.y;
        Bs[kv + 2][r] = vb.z; Bs[kv + 3][r] = vb.w;
        __syncthreads();

        #pragma unroll
        for (int kk = 0; kk < BK; kk++) {
            float a[4], b[4];
            *(float4*)&a[0] = *(const float4*)&As[kk][tm];
            *(float4*)&b[0] = *(const float4*)&Bs[kk][tn];
            #pragma unroll
            for (int i = 0; i < 4; i++)
                #pragma unroll
                for (int j = 0; j < 4; j++)
                    acc[i][j] = fmaf(a[i], b[j], acc[i][j]);
        }
        __syncthreads();
    }

    #pragma unroll
    for (int i = 0; i < 4; i++) {
        *(float4*)(g_p + (size_t)(m0 + tm + i) * N_OUT + n0 + tn) =
            make_float4(acc[i][0], acc[i][1], acc[i][2], acc[i][3]);
    }
}

// ---------------------------------------------------------------------------
// Step 2 (unchanged from R8): cur2 = add.rn(p, b2); LIF; write outputs.
// ---------------------------------------------------------------------------
__global__ __launch_bounds__(256) void step2_kernel(
    const float* __restrict__ b2,
    float* __restrict__ out_spk,
    float* __restrict__ out_mem)
{
    int i = blockIdx.x * blockDim.x + threadIdx.x;
    float4 bb = ((const float4*)b2)[i & 127];
    float4 p = ((const float4*)g_p)[i];
    float4 c;
    c.x = __fadd_rn(p.x, bb.x);
    c.y = __fadd_rn(p.y, bb.y);
    c.z = __fadd_rn(p.z, bb.z);
    c.w = __fadd_rn(p.w, bb.w);
    float4 m = ((const float4*)g_mem2)[i];
    float4 nm, sp;
    lif_update(m.x, c.x, nm.x, sp.x);
    lif_update(m.y, c.y, nm.y, sp.y);
    lif_update(m.z, c.z, nm.z, sp.z);
    lif_update(m.w, c.w, nm.w, sp.w);
    ((float4*)g_mem2)[i]  = nm;
    ((float4*)out_spk)[i] = sp;
    ((float4*)out_mem)[i] = nm;
}

// ---------------------------------------------------------------------------
// Launch — no __device__ symbol addresses taken on the host.
// ---------------------------------------------------------------------------
extern "C" void kernel_launch(void* const* d_in, const int* in_sizes, int n_in,
                              void* d_out, int out_size) {
    const float* x  = (const float*)d_in[0];
    const float* W1 = (const float*)d_in[1];
    const float* b1 = (const float*)d_in[2];
    const float* W2 = (const float*)d_in[3];
    const float* b2 = (const float*)d_in[4];
    float* out = (float*)d_out;

    init_kernel<<<(BATCH * N_HID + 255) / 256, 256>>>();

    {
        dim3 grid(N_HID / 64, (T_STEPS * BATCH) / 128);   // (64, 200)
        gemm1_kernel<<<grid, 256>>>(x, W1, b1);
    }

    float* out_spk_base = out;
    float* out_mem_base = out + (size_t)T_STEPS * BATCH * N_OUT;

    for (int t = 0; t < T_STEPS; t++) {
        step1_kernel<<<(BATCH * N_HID / 4) / 256, 256>>>(t);

        dim3 grid2(N_OUT / 64, BATCH / 64);               // (8, 4)
        gemm2_kernel<<<grid2, 256>>>(W2);

        step2_kernel<<<(BATCH * N_OUT / 4) / 256, 256>>>(
            b2,
            out_spk_base + (size_t)t * BATCH * N_OUT,
            out_mem_base + (size_t)t * BATCH * N_OUT);
    }
}

// round 10
// speedup vs baseline: 2.7626x; 2.7626x over previous
#include <cuda_runtime.h>

// Problem constants
#define T_STEPS 100
#define BATCH   256
#define N_IN    1024
#define N_HID   4096
#define N_OUT   512
#define KHALF   (N_IN / 2)     // gemm1 split-K=2 boundary (validated R9)

#define BETA   0.95f
#define THRESH 1.0f

// ---------------------------------------------------------------------------
// RULE: __device__ globals are referenced ONLY inside device code.
// ---------------------------------------------------------------------------
__device__ float g_cur1[(size_t)T_STEPS * BATCH * N_HID];   // 419 MB
__device__ float g_mem1[BATCH * N_HID];
__device__ float g_spk1[BATCH * N_HID];
__device__ float g_mem2[BATCH * N_OUT];

__global__ void init_kernel() {
    int i = blockIdx.x * blockDim.x + threadIdx.x;
    if (i < BATCH * N_HID) g_mem1[i] = 0.0f;
    if (i < BATCH * N_OUT) g_mem2[i] = 0.0f;
}

// ---------------------------------------------------------------------------
// GEMM1 (VERBATIM R9, bitwise-validated): split-K=2, (p0+p1)+b1.
// Tile 128x64x16, 256 threads, 8x4 per thread, two acc sets.
// ---------------------------------------------------------------------------
__global__ __launch_bounds__(256) void gemm1_kernel(
    const float* __restrict__ A,     // [25600, N_IN]
    const float* __restrict__ W,     // [N_HID, N_IN]
    const float* __restrict__ bias)  // [N_HID]
{
    const int BK = 16;
    __shared__ float As[BK][128];
    __shared__ float Bs[BK][64];

    const int tid = threadIdx.x;
    const int m0 = blockIdx.y * 128;
    const int n0 = blockIdx.x * 64;
    const int tm = (tid >> 4) << 3;   // 0..120
    const int tn = (tid & 15) << 2;   // 0..60

    const int rB  = tid >> 2;         // 0..63
    const int kvB = (tid & 3) << 2;   // 0,4,8,12

    float accA[8][4], accB[8][4];
    #pragma unroll
    for (int i = 0; i < 8; i++)
        #pragma unroll
        for (int j = 0; j < 4; j++) { accA[i][j] = 0.0f; accB[i][j] = 0.0f; }

    for (int k0 = 0; k0 < KHALF; k0 += BK) {
        #pragma unroll
        for (int i = 0; i < 2; i++) {
            int l  = tid + i * 256;
            int r  = l >> 2;
            int kv = (l & 3) << 2;
            float4 va = *(const float4*)(A + (size_t)(m0 + r) * N_IN + k0 + kv);
            As[kv + 0][r] = va.x; As[kv + 1][r] = va.y;
            As[kv + 2][r] = va.z; As[kv + 3][r] = va.w;
        }
        float4 vb = *(const float4*)(W + (size_t)(n0 + rB) * N_IN + k0 + kvB);
        Bs[kvB + 0][rB] = vb.x; Bs[kvB + 1][rB] = vb.y;
        Bs[kvB + 2][rB] = vb.z; Bs[kvB + 3][rB] = vb.w;
        __syncthreads();

        #pragma unroll
        for (int kk = 0; kk < BK; kk++) {
            float a[8], b[4];
            *(float4*)&a[0] = *(const float4*)&As[kk][tm];
            *(float4*)&a[4] = *(const float4*)&As[kk][tm + 4];
            *(float4*)&b[0] = *(const float4*)&Bs[kk][tn];
            #pragma unroll
            for (int i = 0; i < 8; i++)
                #pragma unroll
                for (int j = 0; j < 4; j++)
                    accA[i][j] = fmaf(a[i], b[j], accA[i][j]);
        }
        __syncthreads();
    }

    for (int k0 = KHALF; k0 < N_IN; k0 += BK) {
        #pragma unroll
        for (int i = 0; i < 2; i++) {
            int l  = tid + i * 256;
            int r  = l >> 2;
            int kv = (l & 3) << 2;
            float4 va = *(const float4*)(A + (size_t)(m0 + r) * N_IN + k0 + kv);
            As[kv + 0][r] = va.x; As[kv + 1][r] = va.y;
            As[kv + 2][r] = va.z; As[kv + 3][r] = va.w;
        }
        float4 vb = *(const float4*)(W + (size_t)(n0 + rB) * N_IN + k0 + kvB);
        Bs[kvB + 0][rB] = vb.x; Bs[kvB + 1][rB] = vb.y;
        Bs[kvB + 2][rB] = vb.z; Bs[kvB + 3][rB] = vb.w;
        __syncthreads();

        #pragma unroll
        for (int kk = 0; kk < BK; kk++) {
            float a[8], b[4];
            *(float4*)&a[0] = *(const float4*)&As[kk][tm];
            *(float4*)&a[4] = *(const float4*)&As[kk][tm + 4];
            *(float4*)&b[0] = *(const float4*)&Bs[kk][tn];
            #pragma unroll
            for (int i = 0; i < 8; i++)
                #pragma unroll
                for (int j = 0; j < 4; j++)
                    accB[i][j] = fmaf(a[i], b[j], accB[i][j]);
        }
        __syncthreads();
    }

    float bv[4];
    *(float4*)&bv[0] = *(const float4*)&bias[n0 + tn];

    #pragma unroll
    for (int i = 0; i < 8; i++) {
        float o[4];
        #pragma unroll
        for (int j = 0; j < 4; j++)
            o[j] = __fadd_rn(__fadd_rn(accA[i][j], accB[i][j]), bv[j]);
        *(float4*)(g_cur1 + (size_t)(m0 + tm + i) * N_HID + n0 + tn) =
            make_float4(o[0], o[1], o[2], o[3]);
    }
}

// ---------------------------------------------------------------------------
// LIF update (de-contracted; validated R9)
// ---------------------------------------------------------------------------
__device__ __forceinline__ void lif_update(float m, float c, float& nm, float& sp) {
    float t0 = __fmul_rn(BETA, m);
    float t1 = __fadd_rn(t0, c);
    float rst = (m > THRESH) ? THRESH : 0.0f;
    nm = __fsub_rn(t1, rst);
    sp = (nm > THRESH) ? 1.0f : 0.0f;
}

__global__ __launch_bounds__(256) void step1_kernel(int t) {
    const float* cur1_t = g_cur1 + (size_t)t * BATCH * N_HID;
    int i = blockIdx.x * blockDim.x + threadIdx.x;
    float4 c = ((const float4*)cur1_t)[i];
    float4 m = ((const float4*)g_mem1)[i];
    float4 nm, sp;
    lif_update(m.x, c.x, nm.x, sp.x);
    lif_update(m.y, c.y, nm.y, sp.y);
    lif_update(m.z, c.z, nm.z, sp.z);
    lif_update(m.w, c.w, nm.w, sp.w);
    ((float4*)g_mem1)[i] = nm;
    ((float4*)g_spk1)[i] = sp;
}

// ---------------------------------------------------------------------------
// GEMM2 + fused LIF-2 epilogue (this round's change: parallelism + fusion;
// arithmetic order per output UNCHANGED: single ascending-k fmaf chain,
// then add.rn(acc, b2), then LIF — bitwise identical to R9's gemm2+step2).
// Tile 32x32, BK=32, 256 threads, 2x2 per thread. grid (16, 8) = 128 blocks.
// Register-staged double buffering hides gmem latency.
// ---------------------------------------------------------------------------
__global__ __launch_bounds__(256) void gemm2_fused_kernel(
    const float* __restrict__ W2,    // [N_OUT, N_HID]
    const float* __restrict__ b2,    // [N_OUT]
    float* __restrict__ out_spk,     // [B, N_OUT] slice for this t
    float* __restrict__ out_mem)     // [B, N_OUT] slice for this t
{
    const int BK = 32;
    __shared__ float As[BK][32];   // [k][m] spikes
    __shared__ float Bs[BK][32];   // [k][n] weights

    const int tid = threadIdx.x;
    const int n0 = blockIdx.x * 32;
    const int m0 = blockIdx.y * 32;
    const int tm = (tid >> 4) << 1;   // 0..30
    const int tn = (tid & 15) << 1;   // 0..30
    const int lr = tid >> 3;          // 0..31
    const int lk = (tid & 7) << 2;    // 0,4,...,28

    float acc00 = 0.0f, acc01 = 0.0f, acc10 = 0.0f, acc11 = 0.0f;

    const float* aptr = g_spk1 + (size_t)(m0 + lr) * N_HID + lk;
    const float* bptr = W2     + (size_t)(n0 + lr) * N_HID + lk;

    float4 va = *(const float4*)(aptr);
    float4 vb = *(const float4*)(bptr);

    for (int k0 = 0; k0 < N_HID; k0 += BK) {
        As[lk + 0][lr] = va.x; As[lk + 1][lr] = va.y;
        As[lk + 2][lr] = va.z; As[lk + 3][lr] = va.w;
        Bs[lk + 0][lr] = vb.x; Bs[lk + 1][lr] = vb.y;
        Bs[lk + 2][lr] = vb.z; Bs[lk + 3][lr] = vb.w;
        __syncthreads();

        if (k0 + BK < N_HID) {
            va = *(const float4*)(aptr + k0 + BK);
            vb = *(const float4*)(bptr + k0 + BK);
        }

        #pragma unroll
        for (int kk = 0; kk < BK; kk++) {
            float2 a = *(const float2*)&As[kk][tm];
            float2 b = *(const float2*)&Bs[kk][tn];
            acc00 = fmaf(a.x, b.x, acc00);
            acc01 = fmaf(a.x, b.y, acc01);
            acc10 = fmaf(a.y, b.x, acc10);
            acc11 = fmaf(a.y, b.y, acc11);
        }
        __syncthreads();
    }

    // Fused step2: c = add.rn(acc, b2[n]); LIF; write mem2/spk2/mem_out.
    const int mg = m0 + tm;
    const int ng = n0 + tn;
    const float bbx = b2[ng];
    const float bby = b2[ng + 1];

    {
        float c = __fadd_rn(acc00, bbx);
        float mo = g_mem2[(size_t)mg * N_OUT + ng];
        float nm, sp; lif_update(mo, c, nm, sp);
        g_mem2[(size_t)mg * N_OUT + ng] = nm;
        out_spk[(size_t)mg * N_OUT + ng] = sp;
        out_mem[(size_t)mg * N_OUT + ng] = nm;
    }
    {
        float c = __fadd_rn(acc01, bby);
        float mo = g_mem2[(size_t)mg * N_OUT + ng + 1];
        float nm, sp; lif_update(mo, c, nm, sp);
        g_mem2[(size_t)mg * N_OUT + ng + 1] = nm;
        out_spk[(size_t)mg * N_OUT + ng + 1] = sp;
        out_mem[(size_t)mg * N_OUT + ng + 1] = nm;
    }
    {
        float c = __fadd_rn(acc10, bbx);
        float mo = g_mem2[(size_t)(mg + 1) * N_OUT + ng];
        float nm, sp; lif_update(mo, c, nm, sp);
        g_mem2[(size_t)(mg + 1) * N_OUT + ng] = nm;
        out_spk[(size_t)(mg + 1) * N_OUT + ng] = sp;
        out_mem[(size_t)(mg + 1) * N_OUT + ng] = nm;
    }
    {
        float c = __fadd_rn(acc11, bby);
        float mo = g_mem2[(size_t)(mg + 1) * N_OUT + ng + 1];
        float nm, sp; lif_update(mo, c, nm, sp);
        g_mem2[(size_t)(mg + 1) * N_OUT + ng + 1] = nm;
        out_spk[(size_t)(mg + 1) * N_OUT + ng + 1] = sp;
        out_mem[(size_t)(mg + 1) * N_OUT + ng + 1] = nm;
    }
}

// ---------------------------------------------------------------------------
// Launch — no __device__ symbol addresses taken on the host.
// ---------------------------------------------------------------------------
extern "C" void kernel_launch(void* const* d_in, const int* in_sizes, int n_in,
                              void* d_out, int out_size) {
    const float* x  = (const float*)d_in[0];
    const float* W1 = (const float*)d_in[1];
    const float* b1 = (const float*)d_in[2];
    const float* W2 = (const float*)d_in[3];
    const float* b2 = (const float*)d_in[4];
    float* out = (float*)d_out;

    init_kernel<<<(BATCH * N_HID + 255) / 256, 256>>>();

    {
        dim3 grid(N_HID / 64, (T_STEPS * BATCH) / 128);   // (64, 200)
        gemm1_kernel<<<grid, 256>>>(x, W1, b1);
    }

    float* out_spk_base = out;
    float* out_mem_base = out + (size_t)T_STEPS * BATCH * N_OUT;

    for (int t = 0; t < T_STEPS; t++) {
        step1_kernel<<<(BATCH * N_HID / 4) / 256, 256>>>(t);

        dim3 grid2(N_OUT / 32, BATCH / 32);               // (16, 8) = 128 blocks
        gemm2_fused_kernel<<<grid2, 256>>>(
            W2, b2,
            out_spk_base + (size_t)t * BATCH * N_OUT,
            out_mem_base + (size_t)t * BATCH * N_OUT);
    }
}